// round 6
// baseline (speedup 1.0000x reference)
#include <cuda_runtime.h>
#include <math.h>
#include <stddef.h>

#define NB   2048
#define DL   256
#define XD   256
#define HID  1024
#define CIN  512
#define MAXIT 25

// ---------------- static device scratch (no allocs allowed) ----------------
__device__ float g_W1s[HID * CIN];
__device__ float g_W2s[DL * HID];
__device__ float g_G1[CIN * CIN];    // W1^T W1  (512x512)
__device__ float g_G2[DL * DL];      // W2 W2^T  (256x256)
__device__ float g_invsig[2];
__device__ float g_P[NB * HID];
__device__ float g_H[NB * HID];
__device__ float g_X0[NB * DL];
__device__ float g_Xs[23][NB * DL];   // X history slots t=3..25
__device__ float g_Fs[25][NB * DL];   // F history slots t=0..24

// ---------------- helpers ----------------
__device__ __forceinline__ float red_block(float v, float* red, int tid, int nw) {
    #pragma unroll
    for (int o = 16; o; o >>= 1) v += __shfl_xor_sync(0xffffffffu, v, o);
    if ((tid & 31) == 0) red[tid >> 5] = v;
    __syncthreads();
    if (tid < 32) {
        float x = (tid < nw) ? red[tid] : 0.f;
        #pragma unroll
        for (int o = 16; o; o >>= 1) x += __shfl_xor_sync(0xffffffffu, x, o);
        if (tid == 0) red[0] = x;
    }
    __syncthreads();
    float r = red[0];
    __syncthreads();
    return r;
}

// ---------------- Gram matrix for W1: G1[i][j] = sum_r W1[r][i] W1[r][j] ----
// A = W1 [R x C] row-major; output C x C. Tiles 64x64, BK=16, 256 threads.
template<int R, int C>
__global__ void __launch_bounds__(256) gram_tn(const float* __restrict__ A,
                                               float* __restrict__ Cm) {
    __shared__ float As[16][64 + 4];
    __shared__ float Bs[16][64 + 4];
    int tid = threadIdx.x;
    int bm = blockIdx.y * 64, bn = blockIdx.x * 64;
    int tx = tid % 16, ty = tid / 16;
    float acc[4][4] = {};
    int kk = tid >> 4, c4 = tid & 15;   // 16 k-rows x 16 float4 cols
    for (int k0 = 0; k0 < R; k0 += 16) {
        float4 va = *(const float4*)(A + (size_t)(k0 + kk) * C + bm + c4 * 4);
        As[kk][c4 * 4 + 0] = va.x; As[kk][c4 * 4 + 1] = va.y;
        As[kk][c4 * 4 + 2] = va.z; As[kk][c4 * 4 + 3] = va.w;
        float4 vb = *(const float4*)(A + (size_t)(k0 + kk) * C + bn + c4 * 4);
        Bs[kk][c4 * 4 + 0] = vb.x; Bs[kk][c4 * 4 + 1] = vb.y;
        Bs[kk][c4 * 4 + 2] = vb.z; Bs[kk][c4 * 4 + 3] = vb.w;
        __syncthreads();
        #pragma unroll
        for (int k = 0; k < 16; k++) {
            float a[4], b[4];
            *(float4*)a = *(const float4*)&As[k][ty * 4];
            *(float4*)b = *(const float4*)&Bs[k][tx * 4];
            #pragma unroll
            for (int m = 0; m < 4; m++)
                #pragma unroll
                for (int n = 0; n < 4; n++) acc[m][n] += a[m] * b[n];
        }
        __syncthreads();
    }
    #pragma unroll
    for (int m = 0; m < 4; m++)
        #pragma unroll
        for (int n = 0; n < 4; n++)
            Cm[(size_t)(bm + ty * 4 + m) * C + bn + tx * 4 + n] = acc[m][n];
}

// ---------------- single-block Gram power iteration (2 blocks: W1, W2) -----
__global__ void __launch_bounds__(1024) power_k(const float* __restrict__ W1) {
    __shared__ float t[CIN];
    __shared__ float g2[CIN];
    __shared__ float part[1024];
    __shared__ float red[32];
    int b = blockIdx.x;
    int tid = threadIdx.x, lane = tid & 31, w = tid >> 5;
    const float* G = b ? g_G2 : g_G1;
    const int D   = b ? DL : CIN;        // 256 / 512
    const int NIT = b ? 21 : 20;         // multiplies (last one yields sigma)
    const int RPW = D / 32;              // rows per warp

    // ---- init direction ----
    if (b == 0) {
        // v1 = colsum(W1): thread (c, half) sums 512 rows of column c
        int c = tid & 511, half = tid >> 9;
        float s = 0.f;
        const float* Wp = W1 + (size_t)(half * 512) * CIN + c;
        #pragma unroll 8
        for (int r = 0; r < 512; r++) s += Wp[(size_t)r * CIN];
        part[tid] = s;
        __syncthreads();
        if (tid < CIN) t[tid] = part[tid] + part[tid + 512];
        __syncthreads();
    } else {
        if (tid < DL) t[tid] = 1.f;
        __syncthreads();
    }
    {   // normalize
        float v = (tid < D) ? t[tid] : 0.f;
        float ss = red_block(v * v, red, tid, 32);
        float inv = 1.f / (sqrtf(ss) + 1e-12f);
        if (tid < D) t[tid] *= inv;
        __syncthreads();
    }

    // ---- power iterations on Gram matrix ----
    for (int it = 0; it < NIT; it++) {
        #pragma unroll 2
        for (int rr = 0; rr < RPW; rr++) {
            int j = w * RPW + rr;
            const float4* Gr4 = (const float4*)(G + (size_t)j * D);
            const float4* t4  = (const float4*)t;
            float acc = 0.f;
            #pragma unroll 4
            for (int d = lane; d < D / 4; d += 32) {
                float4 gv = Gr4[d], tv = t4[d];
                acc += gv.x * tv.x + gv.y * tv.y + gv.z * tv.z + gv.w * tv.w;
            }
            #pragma unroll
            for (int o = 16; o; o >>= 1) acc += __shfl_xor_sync(0xffffffffu, acc, o);
            if (lane == 0) g2[j] = acc;
        }
        __syncthreads();
        float gv = (tid < D) ? g2[tid] : 0.f;
        if (it == NIT - 1) {
            float tv = (tid < D) ? t[tid] : 0.f;
            float ssg = red_block(gv * gv, red, tid, 32);
            float dt  = red_block(gv * tv, red, tid, 32);
            if (tid == 0) g_invsig[b] = b ? rsqrtf(dt) : sqrtf(dt / ssg);
        } else {
            float ss = red_block(gv * gv, red, tid, 32);
            float inv = 1.f / (sqrtf(ss) + 1e-12f);
            if (tid < D) t[tid] = g2[tid] * inv;
            __syncthreads();
        }
    }
}

__global__ void scale_k(const float* __restrict__ W1, const float* __restrict__ W2) {
    int i = blockIdx.x * 256 + threadIdx.x;
    const int n1 = HID * CIN;
    const int tot = n1 + DL * HID;
    if (i >= tot) return;
    if (i < n1) g_W1s[i] = W1[i] * g_invsig[0];
    else        g_W2s[i - n1] = W2[i - n1] * g_invsig[1];
}

// ---------------- GEMM (NT: both operands K-major) ----------------
// C[M,N] = act( A[M,K] @ B[N,K]^T + addend ); ADDMODE 0=none,1=vec,2=mat
template<int BM, int BN, int BK, int TM, int TN, bool TANH, int ADDMODE, bool AUXT>
__global__ void __launch_bounds__((BM / TM) * (BN / TN))
gemm_nt(const float* __restrict__ A, int lda,
        const float* __restrict__ Bm, int ldb,
        float* __restrict__ C, int ldc, int K,
        const float* __restrict__ addv, const float* __restrict__ addm,
        float* __restrict__ aux) {
    constexpr int THREADS = (BM / TM) * (BN / TN);
    constexpr int NX = BN / TN;
    __shared__ float As[BK][BM + 4];
    __shared__ float Bs[BK][BN + 4];
    int tid = threadIdx.x;
    int bm = blockIdx.y * BM, bn = blockIdx.x * BN;
    int tx = tid % NX, ty = tid / NX;
    float acc[TM][TN] = {};

    for (int k0 = 0; k0 < K; k0 += BK) {
        #pragma unroll
        for (int i = tid; i < BM * (BK / 4); i += THREADS) {
            int row = i / (BK / 4), c4 = i % (BK / 4);
            float4 v = *(const float4*)(A + (size_t)(bm + row) * lda + k0 + c4 * 4);
            As[c4 * 4 + 0][row] = v.x; As[c4 * 4 + 1][row] = v.y;
            As[c4 * 4 + 2][row] = v.z; As[c4 * 4 + 3][row] = v.w;
        }
        #pragma unroll
        for (int i = tid; i < BN * (BK / 4); i += THREADS) {
            int row = i / (BK / 4), c4 = i % (BK / 4);
            float4 v = *(const float4*)(Bm + (size_t)(bn + row) * ldb + k0 + c4 * 4);
            Bs[c4 * 4 + 0][row] = v.x; Bs[c4 * 4 + 1][row] = v.y;
            Bs[c4 * 4 + 2][row] = v.z; Bs[c4 * 4 + 3][row] = v.w;
        }
        __syncthreads();
        #pragma unroll
        for (int k = 0; k < BK; k++) {
            float a[TM], b[TN];
            #pragma unroll
            for (int m = 0; m < TM; m += 4)
                *(float4*)&a[m] = *(const float4*)&As[k][ty * TM + m];
            #pragma unroll
            for (int n = 0; n < TN; n += 4)
                *(float4*)&b[n] = *(const float4*)&Bs[k][tx * TN + n];
            #pragma unroll
            for (int m = 0; m < TM; m++)
                #pragma unroll
                for (int n = 0; n < TN; n++) acc[m][n] += a[m] * b[n];
        }
        __syncthreads();
    }

    #pragma unroll
    for (int m = 0; m < TM; m++) {
        int row = bm + ty * TM + m;
        #pragma unroll
        for (int n = 0; n < TN; n++) {
            int col = bn + tx * TN + n;
            float v = acc[m][n];
            if (ADDMODE == 2)      v += addm[(size_t)row * ldc + col];
            else if (ADDMODE == 1) v += addv[col];
            if (TANH) v = tanhf(v);
            C[(size_t)row * ldc + col] = v;
            if (AUXT) aux[(size_t)row * ldc + col] = tanhf(v);
        }
    }
}

// ---------------- Anderson update ----------------
struct AndArgs { const float* Z[6]; const float* F[6]; float* out; };

template<int MK>
__global__ void anderson_k(AndArgs a) {
    constexpr int PC = MK * (MK + 1) / 2 + MK;
    int tid = threadIdx.x;
    size_t idx = (size_t)blockIdx.x * DL + tid;
    float z[MK + 1], f[MK + 1];
    #pragma unroll
    for (int i = 0; i <= MK; i++) { z[i] = a.Z[i][idx]; f[i] = a.F[i][idx]; }
    float dF[MK], dG[MK];
    #pragma unroll
    for (int i = 0; i < MK; i++) {
        float dx = z[i] - z[i + 1];
        dF[i] = f[i] - f[i + 1];
        dG[i] = dF[i] - dx;
    }
    float r = f[0] - z[0];
    float part[PC];
    {
        int c = 0;
        #pragma unroll
        for (int i = 0; i < MK; i++)
            #pragma unroll
            for (int j = i; j < MK; j++) part[c++] = dG[i] * dG[j];
        #pragma unroll
        for (int i = 0; i < MK; i++) part[c++] = dG[i] * r;
    }
    __shared__ float s_part[8][PC];
    int lane = tid & 31, wid = tid >> 5;
    #pragma unroll
    for (int p = 0; p < PC; p++) {
        float v = part[p];
        #pragma unroll
        for (int o = 16; o; o >>= 1) v += __shfl_xor_sync(0xffffffffu, v, o);
        if (lane == 0) s_part[wid][p] = v;
    }
    __syncthreads();
    __shared__ float s_alpha[MK];
    if (tid == 0) {
        float S[PC];
        #pragma unroll
        for (int p = 0; p < PC; p++) {
            float s = 0.f;
            #pragma unroll
            for (int w = 0; w < 8; w++) s += s_part[w][p];
            S[p] = s;
        }
        float A[MK][MK], bv[MK];
        int cc = 0;
        for (int i = 0; i < MK; i++)
            for (int j = i; j < MK; j++) { A[i][j] = S[cc]; A[j][i] = S[cc]; cc++; }
        for (int i = 0; i < MK; i++) A[i][i] += 1e-4f;
        for (int i = 0; i < MK; i++) bv[i] = S[cc++];
        for (int p = 0; p < MK; p++) {
            float ip = 1.f / A[p][p];
            for (int rr = p + 1; rr < MK; rr++) {
                float fc = A[rr][p] * ip;
                for (int q = p; q < MK; q++) A[rr][q] -= fc * A[p][q];
                bv[rr] -= fc * bv[p];
            }
        }
        for (int i = MK - 1; i >= 0; i--) {
            float s = bv[i];
            for (int j = i + 1; j < MK; j++) s -= A[i][j] * s_alpha[j];
            s_alpha[i] = s / A[i][i];
        }
    }
    __syncthreads();
    float o = f[0];
    #pragma unroll
    for (int i = 0; i < MK; i++) o -= dF[i] * s_alpha[i];
    a.out[idx] = o;
}

// ---------------- host orchestration ----------------
extern "C" void kernel_launch(void* const* d_in, const int* in_sizes, int n_in,
                              void* d_out, int out_size) {
    const float* ctx = (const float*)d_in[0];
    const float* W1  = (const float*)d_in[1];
    const float* b1  = (const float*)d_in[2];
    const float* W2  = (const float*)d_in[3];
    const float* b2  = (const float*)d_in[4];
    float* out = (float*)d_out;

    float *pW1s, *pW2s, *pG1, *pG2, *pP, *pH, *pX0, *pXs, *pFs;
    cudaGetSymbolAddress((void**)&pW1s, g_W1s);
    cudaGetSymbolAddress((void**)&pW2s, g_W2s);
    cudaGetSymbolAddress((void**)&pG1, g_G1);
    cudaGetSymbolAddress((void**)&pG2, g_G2);
    cudaGetSymbolAddress((void**)&pP,  g_P);
    cudaGetSymbolAddress((void**)&pH,  g_H);
    cudaGetSymbolAddress((void**)&pX0, g_X0);
    cudaGetSymbolAddress((void**)&pXs, g_Xs);
    cudaGetSymbolAddress((void**)&pFs, g_Fs);

    const size_t ZN = (size_t)NB * DL;

    // --- spectral norm: Gram matrices + single-block power iteration ---
    gram_tn<HID, CIN><<<dim3(CIN / 64, CIN / 64), 256>>>(W1, pG1);
    gemm_nt<64, 64, 16, 4, 4, false, 0, false><<<dim3(DL / 64, DL / 64), 256>>>(
        W2, HID, W2, HID, pG2, DL, HID, nullptr, nullptr, nullptr);
    power_k<<<2, 1024>>>(W1);
    scale_k<<<(HID * CIN + DL * HID + 255) / 256, 256>>>(W1, W2);

    // --- loop-invariant context part: P = ctx @ W1c^T + b1; H = tanh(P) ---
    gemm_nt<128, 64, 16, 8, 4, false, 1, true><<<dim3(HID / 64, NB / 128), 256>>>(
        ctx, XD, pW1s + 256, CIN, pP, HID, XD, b1, nullptr, pH);

    auto Zp = [&](int t) -> float* {
        if (t == 0) return pX0;
        if (t <= 2) return pFs;                         // X[1]=X[2]=F0
        return pXs + (size_t)(t - 3) * ZN;
    };
    auto Fp = [&](int t) -> float* {
        if (t == 0) return pFs;
        if (t <= 2) return pFs + ZN;                    // F[2]=F[1] (duplicated warm-up)
        return pFs + (size_t)t * ZN;
    };

    auto feval = [&](const float* z, float* fo) {
        gemm_nt<128, 64, 16, 8, 4, true, 2, false><<<dim3(HID / 64, NB / 128), 256>>>(
            z, DL, pW1s, CIN, pH, HID, DL, nullptr, pP, nullptr);
        gemm_nt<64, 64, 16, 4, 4, true, 1, false><<<dim3(DL / 64, NB / 64), 256>>>(
            pH, HID, pW2s, HID, fo, DL, HID, b2, nullptr, nullptr);
    };

    // --- warm-up: t=0 (x0 = 0 -> H = tanh(P) already), t=1; t=2 aliased ---
    cudaMemsetAsync(pX0, 0, ZN * sizeof(float), 0);
    gemm_nt<64, 64, 16, 4, 4, true, 1, false><<<dim3(DL / 64, NB / 64), 256>>>(
        pH, HID, pW2s, HID, Fp(0), DL, HID, b2, nullptr, nullptr);
    feval(Fp(0), Fp(1));

    // --- Anderson loop k = 2 .. 24 ---
    for (int k = 2; k < MAXIT; k++) {
        int mk = (k < 5) ? k : 5;
        AndArgs aa{};
        for (int i = 0; i <= mk; i++) { aa.Z[i] = Zp(k - i); aa.F[i] = Fp(k - i); }
        float* xo = (k == MAXIT - 1) ? out : Zp(k + 1);
        aa.out = xo;
        switch (mk) {
            case 2: anderson_k<2><<<NB, DL>>>(aa); break;
            case 3: anderson_k<3><<<NB, DL>>>(aa); break;
            case 4: anderson_k<4><<<NB, DL>>>(aa); break;
            default: anderson_k<5><<<NB, DL>>>(aa); break;
        }
        if (k < MAXIT - 1) feval(xo, Fp(k + 1));
    }
}